// round 5
// baseline (speedup 1.0000x reference)
#include <cuda_runtime.h>
#include <cstdint>
#include <math.h>

#define B_  4
#define N_  2048
#define D_  1024
#define H_  16
#define DH_ 64

// Scratch: projected Q/K/V in [B*H][N][dh] layout, attention output X in [B*N][D]
__device__ float g_Q[B_ * H_ * N_ * DH_];
__device__ float g_K[B_ * H_ * N_ * DH_];
__device__ float g_V[B_ * H_ * N_ * DH_];
__device__ float g_X[B_ * N_ * D_];

__device__ __forceinline__ uint32_t f2tf32(float x) {
    uint32_t r;
    asm("cvt.rna.tf32.f32 %0, %1;" : "=r"(r) : "f"(x));
    return r;
}
__device__ __forceinline__ float ex2f(float x) {
    float y;
    asm("ex2.approx.ftz.f32 %0, %1;" : "=f"(y) : "f"(x));
    return y;
}

__device__ __forceinline__ void mma_tf32_16x8x8(
    float& c0, float& c1, float& c2, float& c3,
    uint32_t a0, uint32_t a1, uint32_t a2, uint32_t a3,
    uint32_t b0, uint32_t b1)
{
    asm volatile(
        "mma.sync.aligned.m16n8k8.row.col.f32.tf32.tf32.f32 "
        "{%0,%1,%2,%3}, {%4,%5,%6,%7}, {%8,%9}, {%0,%1,%2,%3};"
        : "+f"(c0), "+f"(c1), "+f"(c2), "+f"(c3)
        : "r"(a0), "r"(a1), "r"(a2), "r"(a3), "r"(b0), "r"(b1));
}

__device__ __forceinline__ void cp16(uint32_t dst, const void* src) {
    asm volatile("cp.async.cg.shared.global [%0], [%1], 16;" :: "r"(dst), "l"(src));
}
__device__ __forceinline__ void cp_commit() {
    asm volatile("cp.async.commit_group;" ::: "memory");
}
template <int N>
__device__ __forceinline__ void cp_wait() {
    asm volatile("cp.async.wait_group %0;" :: "n"(N) : "memory");
}

// ===========================================================================
// tf32 mma.sync GEMM: C[M,1024] = A[M,1024] @ W^T (+bias), W row-major [N][K].
// CTA tile 128x128, k-tile 32. 8 warps (4 m x 2 n), warp tile 32x64.
// cp.async 2-stage pipeline; f32 in smem; cvt.rna -> tf32 at fragment load.
// ===========================================================================
#define KSTR 36                              // padded k stride (floats)
#define MAT_FLOATS (128 * KSTR)              // one 128x32 tile (padded)
#define STAGE_FLOATS (2 * MAT_FLOATS)        // A + B
#define GEMM_SMEM (2 * STAGE_FLOATS * 4)     // 2 stages

template <bool OUT_HEADS, bool HAS_BIAS>
__device__ __forceinline__ void gemm_mma_body(
    const float* __restrict__ A, const float* __restrict__ W,
    const float* __restrict__ bias, float* __restrict__ out)
{
    extern __shared__ float gsm[];
    const uint32_t sbase = (uint32_t)__cvta_generic_to_shared(gsm);

    const int tid  = threadIdx.x;
    const int wid  = tid >> 5;
    const int lane = tid & 31;
    const int g    = lane >> 2;
    const int tig  = lane & 3;
    const int wm   = wid & 3;
    const int wn   = wid >> 2;
    const int m0   = blockIdx.y * 128;
    const int n0   = blockIdx.x * 128;

    // per-thread producer coordinates: 4 float4 slots each for A and B
    const int prow = tid >> 1;               // 0..127, two threads per row
    const int pq   = (tid & 1) * 4;          // float4 index 0..7 (covers 4..7 via +1..3? no)
    // Each thread copies 4 float4: rows prow, float4 cols pq..pq+3? That is 2 threads x 8 f4 per row.
    // slots: thread handles (prow, pq + j) for j in 0..3.

    float c[2][8][4];
#pragma unroll
    for (int t = 0; t < 2; t++)
#pragma unroll
        for (int j = 0; j < 8; j++)
#pragma unroll
            for (int e = 0; e < 4; e++) c[t][j][e] = 0.f;

    const float* Abase = A + (size_t)m0 * D_;
    const float* Wbase = W + (size_t)n0 * D_;

    // issue cp.async for k-tile kt into stage s
    auto issue = [&](int kt, int s) {
        const uint32_t sA = sbase + (uint32_t)(s * STAGE_FLOATS) * 4u;
        const uint32_t sB = sA + (uint32_t)MAT_FLOATS * 4u;
        const float* Ag = Abase + kt * 32;
        const float* Wg = Wbase + kt * 32;
#pragma unroll
        for (int j = 0; j < 4; j++) {
            int q = pq + j;                   // wait: pq in {0,4}; q = 0..3 or 4..7
            cp16(sA + ((uint32_t)prow * KSTR + q * 4) * 4u,
                 Ag + (size_t)prow * D_ + q * 4);
            cp16(sB + ((uint32_t)prow * KSTR + q * 4) * 4u,
                 Wg + (size_t)prow * D_ + q * 4);
        }
    };

    issue(0, 0);
    cp_commit();

    const int NK = D_ / 32;
    for (int kt = 0; kt < NK; kt++) {
        if (kt + 1 < NK) {
            issue(kt + 1, (kt + 1) & 1);
            cp_commit();
            cp_wait<1>();
        } else {
            cp_wait<0>();
        }
        __syncthreads();

        const float* As = gsm + (kt & 1) * STAGE_FLOATS;
        const float* Bs = As + MAT_FLOATS;

#pragma unroll
        for (int kk = 0; kk < 32; kk += 8) {
            uint32_t a[2][4];
#pragma unroll
            for (int t = 0; t < 2; t++) {
                int r = (wm * 32 + t * 16 + g) * KSTR + kk + tig;
                a[t][0] = f2tf32(As[r]);
                a[t][1] = f2tf32(As[r + 8 * KSTR]);
                a[t][2] = f2tf32(As[r + 4]);
                a[t][3] = f2tf32(As[r + 8 * KSTR + 4]);
            }
            uint32_t b[8][2];
#pragma unroll
            for (int j = 0; j < 8; j++) {
                int r = (wn * 64 + j * 8 + g) * KSTR + kk + tig;
                b[j][0] = f2tf32(Bs[r]);
                b[j][1] = f2tf32(Bs[r + 4]);
            }
#pragma unroll
            for (int t = 0; t < 2; t++)
#pragma unroll
                for (int j = 0; j < 8; j++)
                    mma_tf32_16x8x8(c[t][j][0], c[t][j][1], c[t][j][2], c[t][j][3],
                                    a[t][0], a[t][1], a[t][2], a[t][3],
                                    b[j][0], b[j][1]);
        }
        __syncthreads();
    }

#pragma unroll
    for (int t = 0; t < 2; t++) {
        const int r0 = m0 + wm * 32 + t * 16 + g;
#pragma unroll
        for (int j = 0; j < 8; j++) {
            const int col = n0 + wn * 64 + j * 8 + tig * 2;
            float2 v0 = make_float2(c[t][j][0], c[t][j][1]);
            float2 v1 = make_float2(c[t][j][2], c[t][j][3]);
            if (HAS_BIAS) {
                float2 bv = *(const float2*)(bias + col);
                v0.x += bv.x; v0.y += bv.y;
                v1.x += bv.x; v1.y += bv.y;
            }
            if (OUT_HEADS) {
                const int h = col >> 6;
                const int di = col & 63;
                const int b0i = r0 >> 11, n0i = r0 & 2047;
                const int r1 = r0 + 8;
                const int b1i = r1 >> 11, n1i = r1 & 2047;
                *(float2*)(out + (((size_t)(b0i * H_ + h)) * N_ + n0i) * DH_ + di) = v0;
                *(float2*)(out + (((size_t)(b1i * H_ + h)) * N_ + n1i) * DH_ + di) = v1;
            } else {
                *(float2*)(out + (size_t)r0 * D_ + col) = v0;
                *(float2*)(out + (size_t)(r0 + 8) * D_ + col) = v1;
            }
        }
    }
}

__global__ __launch_bounds__(256, 2)
void proj_qkv_mma(const float* __restrict__ xq, const float* __restrict__ xk,
                  const float* __restrict__ xv,
                  const float* __restrict__ Wq, const float* __restrict__ bq,
                  const float* __restrict__ Wk, const float* __restrict__ bk,
                  const float* __restrict__ Wv, const float* __restrict__ bv)
{
    int z = blockIdx.z;
    const float* A = (z == 0) ? xq : (z == 1) ? xk : xv;
    const float* W = (z == 0) ? Wq : (z == 1) ? Wk : Wv;
    const float* b = (z == 0) ? bq : (z == 1) ? bk : bv;
    float* out = (z == 0) ? g_Q : (z == 1) ? g_K : g_V;
    gemm_mma_body<true, true>(A, W, b, out);
}

__global__ __launch_bounds__(256, 2)
void proj_out_mma(const float* __restrict__ Wo, float* __restrict__ out)
{
    gemm_mma_body<false, false>(g_X, Wo, nullptr, out);
}

// ===========================================================================
// Tensor-core flash attention (tf32 mma.sync), causal, dh=64.
// CTA: 128 threads (4 warps). 64-query tile; warp w owns rows w*16..w*16+15.
// Reversed q-tile order so long (high-qt) CTAs launch first.
// ===========================================================================
#define QSTR 68
#define VSTR 72
#define FL_SMEM ((64 * QSTR * 2 + 64 * VSTR) * 4)

__global__ __launch_bounds__(128, 4) void flash_mma_kernel()
{
    extern __shared__ uint32_t fsm[];
    uint32_t* Qs = fsm;                 // [64][QSTR]
    uint32_t* Ks = Qs + 64 * QSTR;      // [64][QSTR]
    uint32_t* Vs = Ks + 64 * QSTR;      // [64][VSTR]

    const int tid  = threadIdx.x;
    const int wq   = tid >> 5;
    const int lane = tid & 31;
    const int g    = lane >> 2;
    const int tig  = lane & 3;
    const int qt   = gridDim.x - 1 - blockIdx.x;   // long CTAs first
    const int bh   = blockIdx.y;
    const int qi0  = qt * 64;

    const float* Qg = g_Q + (size_t)bh * N_ * DH_;
    const float* Kg = g_K + (size_t)bh * N_ * DH_;
    const float* Vg = g_V + (size_t)bh * N_ * DH_;

    const float qscale = 0.125f * 1.44269504088896340736f; // dh^-0.5 * log2(e)

#pragma unroll
    for (int u = 0; u < 8; u++) {
        int f  = tid + 128 * u;
        int r  = f >> 4;
        int dv = f & 15;
        float4 v = *(const float4*)(Qg + (size_t)(qi0 + r) * DH_ + dv * 4);
        uint4 t;
        t.x = f2tf32(v.x * qscale); t.y = f2tf32(v.y * qscale);
        t.z = f2tf32(v.z * qscale); t.w = f2tf32(v.w * qscale);
        *(uint4*)&Qs[r * QSTR + dv * 4] = t;
    }

    float m0r = -1e30f, m1r = -1e30f;
    float l0r = 0.f, l1r = 0.f;
    float O[8][4];
#pragma unroll
    for (int j = 0; j < 8; j++)
#pragma unroll
        for (int e = 0; e < 4; e++) O[j][e] = 0.f;

    const int row0 = qi0 + wq * 16 + g;
    const int row1 = row0 + 8;

    for (int kt2 = 0; kt2 <= qt; kt2++) {
        const int kj0 = kt2 * 64;
        __syncthreads();

#pragma unroll
        for (int u = 0; u < 8; u++) {
            int f  = tid + 128 * u;
            int r  = f >> 4;
            int dv = f & 15;
            float4 kv = *(const float4*)(Kg + (size_t)(kj0 + r) * DH_ + dv * 4);
            uint4 kt_;
            kt_.x = f2tf32(kv.x); kt_.y = f2tf32(kv.y);
            kt_.z = f2tf32(kv.z); kt_.w = f2tf32(kv.w);
            *(uint4*)&Ks[r * QSTR + dv * 4] = kt_;
            float4 vv = *(const float4*)(Vg + (size_t)(kj0 + r) * DH_ + dv * 4);
            uint4 vt;
            vt.x = f2tf32(vv.x); vt.y = f2tf32(vv.y);
            vt.z = f2tf32(vv.z); vt.w = f2tf32(vv.w);
            *(uint4*)&Vs[r * VSTR + dv * 4] = vt;
        }
        __syncthreads();

        float S[8][4];
#pragma unroll
        for (int j = 0; j < 8; j++)
#pragma unroll
            for (int e = 0; e < 4; e++) S[j][e] = 0.f;

#pragma unroll
        for (int kb = 0; kb < 8; kb++) {
            const int ar = (wq * 16 + g) * QSTR + kb * 8 + tig;
            uint32_t a0 = Qs[ar];
            uint32_t a1 = Qs[ar + 8 * QSTR];
            uint32_t a2 = Qs[ar + 4];
            uint32_t a3 = Qs[ar + 8 * QSTR + 4];
#pragma unroll
            for (int j = 0; j < 8; j++) {
                const int br = (j * 8 + g) * QSTR + kb * 8 + tig;
                uint32_t b0 = Ks[br];
                uint32_t b1 = Ks[br + 4];
                mma_tf32_16x8x8(S[j][0], S[j][1], S[j][2], S[j][3],
                                a0, a1, a2, a3, b0, b1);
            }
        }

        if (kt2 == qt) {
#pragma unroll
            for (int j = 0; j < 8; j++) {
                int c = kj0 + j * 8 + tig * 2;
                if (c     > row0) S[j][0] = -1e30f;
                if (c + 1 > row0) S[j][1] = -1e30f;
                if (c     > row1) S[j][2] = -1e30f;
                if (c + 1 > row1) S[j][3] = -1e30f;
            }
        }

        float rmax0 = -1e30f, rmax1 = -1e30f;
#pragma unroll
        for (int j = 0; j < 8; j++) {
            rmax0 = fmaxf(rmax0, fmaxf(S[j][0], S[j][1]));
            rmax1 = fmaxf(rmax1, fmaxf(S[j][2], S[j][3]));
        }
        rmax0 = fmaxf(rmax0, __shfl_xor_sync(0xffffffffu, rmax0, 1));
        rmax0 = fmaxf(rmax0, __shfl_xor_sync(0xffffffffu, rmax0, 2));
        rmax1 = fmaxf(rmax1, __shfl_xor_sync(0xffffffffu, rmax1, 1));
        rmax1 = fmaxf(rmax1, __shfl_xor_sync(0xffffffffu, rmax1, 2));

        float mn0 = fmaxf(m0r, rmax0);
        float mn1 = fmaxf(m1r, rmax1);
        float al0 = ex2f(m0r - mn0);
        float al1 = ex2f(m1r - mn1);
        m0r = mn0; m1r = mn1;

        float sum0 = 0.f, sum1 = 0.f;
        uint32_t P[8][4];
#pragma unroll
        for (int j = 0; j < 8; j++) {
            float p0 = ex2f(S[j][0] - mn0);
            float p1 = ex2f(S[j][1] - mn0);
            float p2 = ex2f(S[j][2] - mn1);
            float p3 = ex2f(S[j][3] - mn1);
            sum0 += p0 + p1;
            sum1 += p2 + p3;
            P[j][0] = f2tf32(p0); P[j][1] = f2tf32(p1);
            P[j][2] = f2tf32(p2); P[j][3] = f2tf32(p3);
        }
        sum0 += __shfl_xor_sync(0xffffffffu, sum0, 1);
        sum0 += __shfl_xor_sync(0xffffffffu, sum0, 2);
        sum1 += __shfl_xor_sync(0xffffffffu, sum1, 1);
        sum1 += __shfl_xor_sync(0xffffffffu, sum1, 2);
        l0r = l0r * al0 + sum0;
        l1r = l1r * al1 + sum1;

#pragma unroll
        for (int j = 0; j < 8; j++) {
            O[j][0] *= al0; O[j][1] *= al0;
            O[j][2] *= al1; O[j][3] *= al1;
        }

        const int srcA = (lane & ~3) | (tig >> 1);
        const int srcB = srcA + 2;
        const bool oddc = (tig & 1);
#pragma unroll
        for (int kb = 0; kb < 8; kb++) {
            uint32_t v0 = __shfl_sync(0xffffffffu, P[kb][0], srcA);
            uint32_t v1 = __shfl_sync(0xffffffffu, P[kb][1], srcA);
            uint32_t a0 = oddc ? v1 : v0;
            uint32_t w0 = __shfl_sync(0xffffffffu, P[kb][0], srcB);
            uint32_t w1 = __shfl_sync(0xffffffffu, P[kb][1], srcB);
            uint32_t a2 = oddc ? w1 : w0;
            uint32_t x0 = __shfl_sync(0xffffffffu, P[kb][2], srcA);
            uint32_t x1 = __shfl_sync(0xffffffffu, P[kb][3], srcA);
            uint32_t a1 = oddc ? x1 : x0;
            uint32_t y0 = __shfl_sync(0xffffffffu, P[kb][2], srcB);
            uint32_t y1 = __shfl_sync(0xffffffffu, P[kb][3], srcB);
            uint32_t a3 = oddc ? y1 : y0;
#pragma unroll
            for (int j = 0; j < 8; j++) {
                uint32_t b0 = Vs[(kb * 8 + tig) * VSTR + j * 8 + g];
                uint32_t b1 = Vs[(kb * 8 + tig + 4) * VSTR + j * 8 + g];
                mma_tf32_16x8x8(O[j][0], O[j][1], O[j][2], O[j][3],
                                a0, a1, a2, a3, b0, b1);
            }
        }
    }

    const int b = bh >> 4;
    const int h = bh & 15;
    const float il0 = 1.f / l0r;
    const float il1 = 1.f / l1r;
    float* X0 = g_X + ((size_t)b * N_ + row0) * D_ + h * DH_;
    float* X1 = g_X + ((size_t)b * N_ + row1) * D_ + h * DH_;
#pragma unroll
    for (int j = 0; j < 8; j++) {
        int e = j * 8 + tig * 2;
        *(float2*)(X0 + e) = make_float2(O[j][0] * il0, O[j][1] * il0);
        *(float2*)(X1 + e) = make_float2(O[j][2] * il1, O[j][3] * il1);
    }
}

// ---------------------------------------------------------------------------
extern "C" void kernel_launch(void* const* d_in, const int* in_sizes, int n_in,
                              void* d_out, int out_size)
{
    const float* q  = (const float*)d_in[0];
    const float* k  = (const float*)d_in[1];
    const float* v  = (const float*)d_in[2];
    const float* Wq = (const float*)d_in[3];
    const float* bq = (const float*)d_in[4];
    const float* Wk = (const float*)d_in[5];
    const float* bk = (const float*)d_in[6];
    const float* Wv = (const float*)d_in[7];
    const float* bv = (const float*)d_in[8];
    const float* Wo = (const float*)d_in[9];
    float* out = (float*)d_out;

    cudaFuncSetAttribute(proj_qkv_mma, cudaFuncAttributeMaxDynamicSharedMemorySize, GEMM_SMEM);
    cudaFuncSetAttribute(proj_out_mma, cudaFuncAttributeMaxDynamicSharedMemorySize, GEMM_SMEM);
    cudaFuncSetAttribute(flash_mma_kernel, cudaFuncAttributeMaxDynamicSharedMemorySize, FL_SMEM);

    // QKV projections
    dim3 gp(8, 64, 3);
    proj_qkv_mma<<<gp, 256, GEMM_SMEM>>>(q, k, v, Wq, bq, Wk, bk, Wv, bv);

    // Tensor-core flash attention: 32 q-tiles x 64 (b,h) pairs
    dim3 gf(N_ / 64, B_ * H_);
    flash_mma_kernel<<<gf, 128, FL_SMEM>>>();

    // Output projection
    dim3 go(8, 64, 1);
    proj_out_mma<<<go, 256, GEMM_SMEM>>>(Wo, out);
}